// round 6
// baseline (speedup 1.0000x reference)
#include <cuda_runtime.h>
#include <cuda_bf16.h>
#include <cstdint>
#include <cstddef>

// Problem constants
#define DIMc 1024
#define Hc   16
#define HDc  64
#define Bc   8
#define Nc   1024
#define SCALEc 0.125f      // HD^-0.5
#define CAPc   50.0f

#define Mtot (Bc * Nc)     // 8192

// ---------------------------------------------------------------------------
// Scratch (__device__ globals; allocation in kernel_launch is forbidden)
// ---------------------------------------------------------------------------
__device__ float g_q [(size_t)Bc * Hc * Nc * HDc];   // [B,H,N,HD] fp32
__device__ float g_k [(size_t)Bc * Hc * Nc * HDc];
__device__ float g_v [(size_t)Bc * Hc * Nc * HDc];
__device__ unsigned char g_mask[(size_t)Nc * Nc];    // canonical 1-byte mask
__device__ int g_maskmode;

// Pre-split bf16 hi/lo operand storage
__device__ __align__(128) __nv_bfloat16 g_xh[(size_t)Mtot * DIMc];
__device__ __align__(128) __nv_bfloat16 g_xl[(size_t)Mtot * DIMc];
__device__ __align__(128) __nv_bfloat16 g_wqh[(size_t)DIMc * DIMc], g_wql[(size_t)DIMc * DIMc];
__device__ __align__(128) __nv_bfloat16 g_wkh[(size_t)DIMc * DIMc], g_wkl[(size_t)DIMc * DIMc];
__device__ __align__(128) __nv_bfloat16 g_wvh[(size_t)DIMc * DIMc], g_wvl[(size_t)DIMc * DIMc];
__device__ __align__(128) __nv_bfloat16 g_woh[(size_t)DIMc * DIMc], g_wol[(size_t)DIMc * DIMc];
__device__ __align__(128) __nv_bfloat16 g_aoh[(size_t)Mtot * DIMc];  // attn out hi
__device__ __align__(128) __nv_bfloat16 g_aol[(size_t)Mtot * DIMc];  // attn out lo

// ---------------------------------------------------------------------------
// Paired-bf16 helpers.  x = hi + lo, hi = bf16(x), lo = bf16(x - hi).
// ---------------------------------------------------------------------------
__device__ __forceinline__ unsigned pack2(float x, float y) {
    __nv_bfloat162 t = __floats2bfloat162_rn(x, y);
    return *reinterpret_cast<unsigned*>(&t);
}
__device__ __forceinline__ float bfhi(float x) {
    return __bfloat162float(__float2bfloat16_rn(x));
}

__device__ __forceinline__ void mma16(float* c, const unsigned* a, unsigned b0, unsigned b1) {
    asm volatile(
        "mma.sync.aligned.m16n8k16.row.col.f32.bf16.bf16.f32 "
        "{%0,%1,%2,%3},{%4,%5,%6,%7},{%8,%9},{%0,%1,%2,%3};"
        : "+f"(c[0]), "+f"(c[1]), "+f"(c[2]), "+f"(c[3])
        : "r"(a[0]), "r"(a[1]), "r"(a[2]), "r"(a[3]), "r"(b0), "r"(b1));
}

__device__ __forceinline__ void cpa16(unsigned* dst_smem, const void* src) {
    unsigned d = (unsigned)__cvta_generic_to_shared(dst_smem);
    asm volatile("cp.async.cg.shared.global [%0], [%1], 16;" :: "r"(d), "l"(src));
}

// ---------------------------------------------------------------------------
// Split fp32 -> bf16 hi/lo (u32-pair stores).  n4 = nelem/4.
// ---------------------------------------------------------------------------
__global__ void __launch_bounds__(256)
split_kernel(const float* __restrict__ src, unsigned* __restrict__ dh,
             unsigned* __restrict__ dl, int n4)
{
    int i = blockIdx.x * 256 + threadIdx.x;
    if (i < n4) {
        float4 v = ((const float4*)src)[i];
        dh[i * 2    ] = pack2(v.x, v.y);
        dh[i * 2 + 1] = pack2(v.z, v.w);
        dl[i * 2    ] = pack2(v.x - bfhi(v.x), v.y - bfhi(v.y));
        dl[i * 2 + 1] = pack2(v.z - bfhi(v.z), v.w - bfhi(v.w));
    }
}

// ---------------------------------------------------------------------------
// Mask normalization (dtype-width detect + canonical uint8), as in R4.
// ---------------------------------------------------------------------------
__global__ void mask_detect_kernel(const unsigned char* __restrict__ m) {
    __shared__ int ok;
    if (threadIdx.x == 0) ok = 1;
    __syncthreads();
    for (int i = threadIdx.x; i < Nc; i += blockDim.x)
        if (m[(size_t)i * (Nc + 1)] == 0) ok = 0;
    __syncthreads();
    if (threadIdx.x == 0) g_maskmode = ok;
}

__global__ void mask_convert_kernel(const unsigned char* __restrict__ mb) {
    int i = blockIdx.x * 256 + threadIdx.x;
    if (g_maskmode) {
        g_mask[i] = (mb[i] != 0);
    } else {
        const unsigned* mw = (const unsigned*)mb;
        g_mask[i] = (mw[i] != 0);
    }
}

// ---------------------------------------------------------------------------
// Pipelined paired-bf16 GEMM on pre-split operands.  C = X @ W^T, K=O=1024.
// MODE 0: plain row-major C (output projection).
// MODE 1: fused QKV via blockIdx.z; C scattered to [B,H,N,HD].
// 2-stage cp.async pipeline; block tile 128x128x32; 8 warps, warp tile 32x64.
// smem: per stage 4 tiles (Ah,Al,Bh,Bl) of 128x20 u32 (bf16-pair view, pad 4).
// ---------------------------------------------------------------------------
#define TILE_U32  (128 * 20)
#define STAGE_U32 (4 * TILE_U32)
#define GEMM_SMEM (2 * STAGE_U32 * 4)   // bytes = 81920

template <int MODE>
__global__ void __launch_bounds__(256)
gemm_async(const __nv_bfloat16* __restrict__ Xh, const __nv_bfloat16* __restrict__ Xl,
           const __nv_bfloat16* __restrict__ Wh0, const __nv_bfloat16* __restrict__ Wl0,
           const __nv_bfloat16* __restrict__ Wh1, const __nv_bfloat16* __restrict__ Wl1,
           const __nv_bfloat16* __restrict__ Wh2, const __nv_bfloat16* __restrict__ Wl2,
           float* __restrict__ C0, float* __restrict__ C1, float* __restrict__ C2)
{
    extern __shared__ unsigned sm[];

    const __nv_bfloat16* Wh = Wh0;
    const __nv_bfloat16* Wl = Wl0;
    float* C = C0;
    if (MODE == 1) {
        if (blockIdx.z == 1)      { Wh = Wh1; Wl = Wl1; C = C1; }
        else if (blockIdx.z == 2) { Wh = Wh2; Wl = Wl2; C = C2; }
    }

    const int tid  = threadIdx.x;
    const int warp = tid >> 5;
    const int lane = tid & 31;
    const int g    = lane >> 2;
    const int tg   = lane & 3;
    const int wm   = (warp >> 1) * 32;
    const int wn   = (warp & 1) * 64;
    const int m0   = blockIdx.y * 128;
    const int o0   = blockIdx.x * 128;

    // per-thread static load coords (2 chunks of 16B per tile per stage)
    const int ch0r = tid >> 2,         ch0c = tid & 3;          // chunk tid
    const int ch1r = (tid + 256) >> 2, ch1c = (tid + 256) & 3;  // chunk tid+256

    float acc[2][8][4];
#pragma unroll
    for (int mt = 0; mt < 2; mt++)
#pragma unroll
        for (int nt = 0; nt < 8; nt++)
#pragma unroll
            for (int i = 0; i < 4; i++) acc[mt][nt][i] = 0.0f;

    auto load_stage = [&](int st, int kt) {
        unsigned* S = sm + st * STAGE_U32;
        const int k0 = kt * 32;
        {
            size_t aoff = (size_t)(m0 + ch0r) * 1024 + k0 + ch0c * 8;
            size_t boff = (size_t)(o0 + ch0r) * 1024 + k0 + ch0c * 8;
            cpa16(S +                ch0r * 20 + ch0c * 4, Xh + aoff);
            cpa16(S + TILE_U32     + ch0r * 20 + ch0c * 4, Xl + aoff);
            cpa16(S + 2 * TILE_U32 + ch0r * 20 + ch0c * 4, Wh + boff);
            cpa16(S + 3 * TILE_U32 + ch0r * 20 + ch0c * 4, Wl + boff);
        }
        {
            size_t aoff = (size_t)(m0 + ch1r) * 1024 + k0 + ch1c * 8;
            size_t boff = (size_t)(o0 + ch1r) * 1024 + k0 + ch1c * 8;
            cpa16(S +                ch1r * 20 + ch1c * 4, Xh + aoff);
            cpa16(S + TILE_U32     + ch1r * 20 + ch1c * 4, Xl + aoff);
            cpa16(S + 2 * TILE_U32 + ch1r * 20 + ch1c * 4, Wh + boff);
            cpa16(S + 3 * TILE_U32 + ch1r * 20 + ch1c * 4, Wl + boff);
        }
        asm volatile("cp.async.commit_group;");
    };

    load_stage(0, 0);

    for (int kt = 0; kt < 32; kt++) {
        if (kt + 1 < 32) {
            load_stage((kt + 1) & 1, kt + 1);
            asm volatile("cp.async.wait_group 1;");
        } else {
            asm volatile("cp.async.wait_group 0;");
        }
        __syncthreads();

        const unsigned* Ah = sm + (kt & 1) * STAGE_U32;
        const unsigned* Al = Ah + TILE_U32;
        const unsigned* Bh = Al + TILE_U32;
        const unsigned* Bl = Bh + TILE_U32;

#pragma unroll
        for (int kc = 0; kc < 2; kc++) {
            unsigned ah[2][4], al[2][4], bh[8][2], bl[8][2];
#pragma unroll
            for (int mt = 0; mt < 2; mt++) {
                int r = wm + mt * 16;
                ah[mt][0] = Ah[(r + g    ) * 20 + kc * 8 + tg    ];
                ah[mt][1] = Ah[(r + g + 8) * 20 + kc * 8 + tg    ];
                ah[mt][2] = Ah[(r + g    ) * 20 + kc * 8 + tg + 4];
                ah[mt][3] = Ah[(r + g + 8) * 20 + kc * 8 + tg + 4];
                al[mt][0] = Al[(r + g    ) * 20 + kc * 8 + tg    ];
                al[mt][1] = Al[(r + g + 8) * 20 + kc * 8 + tg    ];
                al[mt][2] = Al[(r + g    ) * 20 + kc * 8 + tg + 4];
                al[mt][3] = Al[(r + g + 8) * 20 + kc * 8 + tg + 4];
            }
#pragma unroll
            for (int nt = 0; nt < 8; nt++) {
                bh[nt][0] = Bh[(wn + nt * 8 + g) * 20 + kc * 8 + tg    ];
                bh[nt][1] = Bh[(wn + nt * 8 + g) * 20 + kc * 8 + tg + 4];
                bl[nt][0] = Bl[(wn + nt * 8 + g) * 20 + kc * 8 + tg    ];
                bl[nt][1] = Bl[(wn + nt * 8 + g) * 20 + kc * 8 + tg + 4];
            }
#pragma unroll
            for (int mt = 0; mt < 2; mt++)
#pragma unroll
                for (int nt = 0; nt < 8; nt++) {
                    mma16(acc[mt][nt], ah[mt], bh[nt][0], bh[nt][1]);
                    mma16(acc[mt][nt], ah[mt], bl[nt][0], bl[nt][1]);
                    mma16(acc[mt][nt], al[mt], bh[nt][0], bh[nt][1]);
                }
        }
        __syncthreads();
    }

#pragma unroll
    for (int mt = 0; mt < 2; mt++) {
#pragma unroll
        for (int nt = 0; nt < 8; nt++) {
#pragma unroll
            for (int rr = 0; rr < 4; rr++) {
                int r = m0 + wm + mt * 16 + g + ((rr >= 2) ? 8 : 0);
                int c = o0 + wn + nt * 8 + tg * 2 + (rr & 1);
                float val = acc[mt][nt][rr];
                if (MODE == 0) {
                    C[(size_t)r * DIMc + c] = val;
                } else {
                    int bb   = r >> 10;
                    int ntok = r & 1023;
                    int hh   = c >> 6;
                    int dd   = c & 63;
                    C[((((size_t)bb * Hc + hh) * Nc + ntok) << 6) + dd] = val;
                }
            }
        }
    }
}

// ---------------------------------------------------------------------------
// QKNorm + gathered 2D RoPE (fp32, in place). Warp per row.
// ---------------------------------------------------------------------------
__global__ void __launch_bounds__(128)
qknorm_rope_kernel(const float* __restrict__ qg, const float* __restrict__ kg,
                   const float* __restrict__ cost, const float* __restrict__ sint,
                   const int* __restrict__ ridx)
{
    int row  = blockIdx.x * 4 + (threadIdx.x >> 5);
    int lane = threadIdx.x & 31;
    int ntok = row & (Nc - 1);

    float* qr = g_q + (size_t)row * HDc;
    float* kr = g_k + (size_t)row * HDc;

    float q0 = qr[lane], q1 = qr[lane + 32];
    float k0 = kr[lane], k1 = kr[lane + 32];

    float sq = q0 * q0 + q1 * q1;
    float sk = k0 * k0 + k1 * k1;
#pragma unroll
    for (int off = 16; off >= 1; off >>= 1) {
        sq += __shfl_xor_sync(0xffffffffu, sq, off);
        sk += __shfl_xor_sync(0xffffffffu, sk, off);
    }
    float rq = rsqrtf(sq * (1.0f / 64.0f) + 1e-6f);
    float rk = rsqrtf(sk * (1.0f / 64.0f) + 1e-6f);
    q0 *= rq * qg[lane]; q1 *= rq * qg[lane + 32];
    k0 *= rk * kg[lane]; k1 *= rk * kg[lane + 32];

    int idx = ridx[ntok];
    if (idx >= 0) {
        const float* cr = cost + (size_t)idx * HDc;
        const float* sr = sint + (size_t)idx * HDc;
        float c0 = cr[lane], c1 = cr[lane + 32];
        float s0 = sr[lane], s1 = sr[lane + 32];
        float nq0 = q0 * c0 - q1 * s0;
        float nq1 = q1 * c1 + q0 * s1;
        float nk0 = k0 * c0 - k1 * s0;
        float nk1 = k1 * c1 + k0 * s1;
        q0 = nq0; q1 = nq1; k0 = nk0; k1 = nk1;
    }
    qr[lane] = q0; qr[lane + 32] = q1;
    kr[lane] = k0; kr[lane + 32] = k1;
}

// ---------------------------------------------------------------------------
// Flash attention (paired-bf16 MMAs). Softcap via odd Taylor poly:
// after QKNorm |q|=|k|=8 so |s*SCALE/CAP| <= 0.16 -> deg-7 error < 1e-8.
// Epilogue writes split bf16 (g_aoh/g_aol) for the pipelined out-projection.
// ---------------------------------------------------------------------------
__global__ void __launch_bounds__(128)
attn_kernel()
{
    __shared__ unsigned Kh[64][36], Kl[64][36];
    __shared__ unsigned short Vh[64][72], Vl[64][72];

    const int b  = blockIdx.z;
    const int h  = blockIdx.y;
    const int q0 = blockIdx.x * 64;
    const size_t base = ((size_t)b * Hc + h) * Nc * HDc;
    const float* qp = g_q + base;
    const float* kp = g_k + base;
    const float* vp = g_v + base;

    const int tid  = threadIdx.x;
    const int warp = tid >> 5;
    const int lane = tid & 31;
    const int g    = lane >> 2;
    const int tg   = lane & 3;
    const int wm   = warp * 16;

#pragma unroll
    for (int i = 0; i < 8; i++) {
        int idx = tid + i * 128;
        int r = idx >> 4, c4 = idx & 15;
        float4 v4 = *(const float4*)(qp + (size_t)(q0 + r) * HDc + c4 * 4);
        Kh[r][c4 * 2    ] = pack2(v4.x, v4.y);
        Kh[r][c4 * 2 + 1] = pack2(v4.z, v4.w);
        Kl[r][c4 * 2    ] = pack2(v4.x - bfhi(v4.x), v4.y - bfhi(v4.y));
        Kl[r][c4 * 2 + 1] = pack2(v4.z - bfhi(v4.z), v4.w - bfhi(v4.w));
    }
    __syncthreads();
    unsigned qh[4][4], ql[4][4];
#pragma unroll
    for (int kc = 0; kc < 4; kc++) {
        qh[kc][0] = Kh[wm + g    ][kc * 8 + tg    ];
        qh[kc][1] = Kh[wm + g + 8][kc * 8 + tg    ];
        qh[kc][2] = Kh[wm + g    ][kc * 8 + tg + 4];
        qh[kc][3] = Kh[wm + g + 8][kc * 8 + tg + 4];
        ql[kc][0] = Kl[wm + g    ][kc * 8 + tg    ];
        ql[kc][1] = Kl[wm + g + 8][kc * 8 + tg    ];
        ql[kc][2] = Kl[wm + g    ][kc * 8 + tg + 4];
        ql[kc][3] = Kl[wm + g + 8][kc * 8 + tg + 4];
    }
    __syncthreads();

    float oacc[8][4];
#pragma unroll
    for (int nt = 0; nt < 8; nt++)
#pragma unroll
        for (int i = 0; i < 4; i++) oacc[nt][i] = 0.0f;

    float m_i[2] = {-1e30f, -1e30f};
    float l_i[2] = {0.0f, 0.0f};
    const unsigned* Vh32 = (const unsigned*)&Vh[0][0];
    const unsigned* Vl32 = (const unsigned*)&Vl[0][0];

    for (int kv0 = 0; kv0 < Nc; kv0 += 64) {
#pragma unroll
        for (int i = 0; i < 8; i++) {
            int idx = tid + i * 128;
            int r = idx >> 4, c4 = idx & 15;
            float4 kk = *(const float4*)(kp + (size_t)(kv0 + r) * HDc + c4 * 4);
            Kh[r][c4 * 2    ] = pack2(kk.x, kk.y);
            Kh[r][c4 * 2 + 1] = pack2(kk.z, kk.w);
            Kl[r][c4 * 2    ] = pack2(kk.x - bfhi(kk.x), kk.y - bfhi(kk.y));
            Kl[r][c4 * 2 + 1] = pack2(kk.z - bfhi(kk.z), kk.w - bfhi(kk.w));
            float4 vv = *(const float4*)(vp + (size_t)(kv0 + r) * HDc + c4 * 4);
            float f[4] = {vv.x, vv.y, vv.z, vv.w};
#pragma unroll
            for (int j = 0; j < 4; j++) {
                int d = c4 * 4 + j;
                __nv_bfloat16 hv = __float2bfloat16_rn(f[j]);
                Vh[d][r] = *reinterpret_cast<unsigned short*>(&hv);
                __nv_bfloat16 lv = __float2bfloat16_rn(f[j] - __bfloat162float(hv));
                Vl[d][r] = *reinterpret_cast<unsigned short*>(&lv);
            }
        }
        __syncthreads();

        float s[8][4];
#pragma unroll
        for (int nt = 0; nt < 8; nt++)
#pragma unroll
            for (int i = 0; i < 4; i++) s[nt][i] = 0.0f;

#pragma unroll
        for (int kc = 0; kc < 4; kc++) {
#pragma unroll
            for (int nt = 0; nt < 8; nt++) {
                unsigned bh0 = Kh[nt * 8 + g][kc * 8 + tg    ];
                unsigned bh1 = Kh[nt * 8 + g][kc * 8 + tg + 4];
                unsigned bl0 = Kl[nt * 8 + g][kc * 8 + tg    ];
                unsigned bl1 = Kl[nt * 8 + g][kc * 8 + tg + 4];
                mma16(s[nt], qh[kc], bh0, bh1);
                mma16(s[nt], qh[kc], bl0, bl1);
                mma16(s[nt], ql[kc], bh0, bh1);
            }
        }

        // softcap (poly tanh) + mask
        const int qr0 = q0 + wm + g;
#pragma unroll
        for (int nt = 0; nt < 8; nt++) {
#pragma unroll
            for (int rr = 0; rr < 4; rr++) {
                int qrow = qr0 + ((rr >= 2) ? 8 : 0);
                int kvc  = kv0 + nt * 8 + tg * 2 + (rr & 1);
                float z = s[nt][rr] * SCALEc;                // = CAP * x, x = s*SCALE/CAP
                float t = z * z * (1.0f / (CAPc * CAPc));    // x^2
                float sv = z * (1.0f + t * (-0.33333333f +
                                t * (0.13333333f + t * (-0.05396825f))));
                sv = g_mask[(size_t)qrow * Nc + kvc] ? sv : -1e30f;
                s[nt][rr] = sv;
            }
        }

        // online softmax
        float tm0 = -1e30f, tm1 = -1e30f;
#pragma unroll
        for (int nt = 0; nt < 8; nt++) {
            tm0 = fmaxf(tm0, fmaxf(s[nt][0], s[nt][1]));
            tm1 = fmaxf(tm1, fmaxf(s[nt][2], s[nt][3]));
        }
        tm0 = fmaxf(tm0, __shfl_xor_sync(0xffffffffu, tm0, 1));
        tm0 = fmaxf(tm0, __shfl_xor_sync(0xffffffffu, tm0, 2));
        tm1 = fmaxf(tm1, __shfl_xor_sync(0xffffffffu, tm1, 1));
        tm1 = fmaxf(tm1, __shfl_xor_sync(0xffffffffu, tm1, 2));

        float mn0 = fmaxf(m_i[0], tm0);
        float mn1 = fmaxf(m_i[1], tm1);
        float cr0 = __expf(m_i[0] - mn0);
        float cr1 = __expf(m_i[1] - mn1);
        m_i[0] = mn0; m_i[1] = mn1;

        float ps0 = 0.0f, ps1 = 0.0f;
#pragma unroll
        for (int nt = 0; nt < 8; nt++) {
            s[nt][0] = __expf(s[nt][0] - mn0); ps0 += s[nt][0];
            s[nt][1] = __expf(s[nt][1] - mn0); ps0 += s[nt][1];
            s[nt][2] = __expf(s[nt][2] - mn1); ps1 += s[nt][2];
            s[nt][3] = __expf(s[nt][3] - mn1); ps1 += s[nt][3];
        }
        ps0 += __shfl_xor_sync(0xffffffffu, ps0, 1);
        ps0 += __shfl_xor_sync(0xffffffffu, ps0, 2);
        ps1 += __shfl_xor_sync(0xffffffffu, ps1, 1);
        ps1 += __shfl_xor_sync(0xffffffffu, ps1, 2);
        l_i[0] = l_i[0] * cr0 + ps0;
        l_i[1] = l_i[1] * cr1 + ps1;

#pragma unroll
        for (int nt = 0; nt < 8; nt++) {
            oacc[nt][0] *= cr0; oacc[nt][1] *= cr0;
            oacc[nt][2] *= cr1; oacc[nt][3] *= cr1;
        }

        // O += P V  (P fragments straight from C fragments; no shuffles)
#pragma unroll
        for (int kc = 0; kc < 4; kc++) {
            unsigned ph[4], pl[4];
            float p00 = s[2 * kc][0],     p01 = s[2 * kc][1];
            float p10 = s[2 * kc][2],     p11 = s[2 * kc][3];
            float p20 = s[2 * kc + 1][0], p21 = s[2 * kc + 1][1];
            float p30 = s[2 * kc + 1][2], p31 = s[2 * kc + 1][3];
            ph[0] = pack2(p00, p01); pl[0] = pack2(p00 - bfhi(p00), p01 - bfhi(p01));
            ph[1] = pack2(p10, p11); pl[1] = pack2(p10 - bfhi(p10), p11 - bfhi(p11));
            ph[2] = pack2(p20, p21); pl[2] = pack2(p20 - bfhi(p20), p21 - bfhi(p21));
            ph[3] = pack2(p30, p31); pl[3] = pack2(p30 - bfhi(p30), p31 - bfhi(p31));
#pragma unroll
            for (int nt = 0; nt < 8; nt++) {
                unsigned vh0 = Vh32[(nt * 8 + g) * 36 + kc * 8 + tg    ];
                unsigned vh1 = Vh32[(nt * 8 + g) * 36 + kc * 8 + tg + 4];
                unsigned vl0 = Vl32[(nt * 8 + g) * 36 + kc * 8 + tg    ];
                unsigned vl1 = Vl32[(nt * 8 + g) * 36 + kc * 8 + tg + 4];
                mma16(oacc[nt], ph, vh0, vh1);
                mma16(oacc[nt], ph, vl0, vl1);
                mma16(oacc[nt], pl, vh0, vh1);
            }
        }
        __syncthreads();
    }

    // epilogue: O/l, write split bf16 pairs into g_aoh/g_aol [B,N,DIM]
    float il0 = 1.0f / l_i[0];
    float il1 = 1.0f / l_i[1];
    unsigned* aoh = (unsigned*)g_aoh;
    unsigned* aol = (unsigned*)g_aol;
    const int qr0a = q0 + wm + g;
#pragma unroll
    for (int nt = 0; nt < 8; nt++) {
        float v0 = oacc[nt][0] * il0, v1 = oacc[nt][1] * il0;
        size_t e0 = ((size_t)(b * Nc + qr0a) * DIMc + h * HDc + nt * 8 + tg * 2) >> 1;
        aoh[e0] = pack2(v0, v1);
        aol[e0] = pack2(v0 - bfhi(v0), v1 - bfhi(v1));
        float w0 = oacc[nt][2] * il1, w1 = oacc[nt][3] * il1;
        size_t e1 = ((size_t)(b * Nc + qr0a + 8) * DIMc + h * HDc + nt * 8 + tg * 2) >> 1;
        aoh[e1] = pack2(w0, w1);
        aol[e1] = pack2(w0 - bfhi(w0), w1 - bfhi(w1));
    }
}

// ---------------------------------------------------------------------------
// kernel_launch. Inputs: x, Wq, Wk, Wv, Wo, q_gamma, k_gamma, cos, sin,
//                        rope_indices, mask
// ---------------------------------------------------------------------------
extern "C" void kernel_launch(void* const* d_in, const int* in_sizes, int n_in,
                              void* d_out, int out_size)
{
    const float* x    = (const float*)d_in[0];
    const float* Wq   = (const float*)d_in[1];
    const float* Wk   = (const float*)d_in[2];
    const float* Wv   = (const float*)d_in[3];
    const float* Wo   = (const float*)d_in[4];
    const float* qg   = (const float*)d_in[5];
    const float* kg   = (const float*)d_in[6];
    const float* cost = (const float*)d_in[7];
    const float* sint = (const float*)d_in[8];
    const int*   ridx = (const int*)d_in[9];
    const unsigned char* maskraw = (const unsigned char*)d_in[10];
    float* out = (float*)d_out;

    float *gq, *gk, *gv;
    cudaGetSymbolAddress((void**)&gq, g_q);
    cudaGetSymbolAddress((void**)&gk, g_k);
    cudaGetSymbolAddress((void**)&gv, g_v);

    __nv_bfloat16 *xh, *xl, *wqh, *wql, *wkh, *wkl, *wvh, *wvl, *woh, *wol, *aoh, *aol;
    cudaGetSymbolAddress((void**)&xh,  g_xh);  cudaGetSymbolAddress((void**)&xl,  g_xl);
    cudaGetSymbolAddress((void**)&wqh, g_wqh); cudaGetSymbolAddress((void**)&wql, g_wql);
    cudaGetSymbolAddress((void**)&wkh, g_wkh); cudaGetSymbolAddress((void**)&wkl, g_wkl);
    cudaGetSymbolAddress((void**)&wvh, g_wvh); cudaGetSymbolAddress((void**)&wvl, g_wvl);
    cudaGetSymbolAddress((void**)&woh, g_woh); cudaGetSymbolAddress((void**)&wol, g_wol);
    cudaGetSymbolAddress((void**)&aoh, g_aoh); cudaGetSymbolAddress((void**)&aol, g_aol);

    cudaFuncSetAttribute(gemm_async<0>, cudaFuncAttributeMaxDynamicSharedMemorySize, GEMM_SMEM);
    cudaFuncSetAttribute(gemm_async<1>, cudaFuncAttributeMaxDynamicSharedMemorySize, GEMM_SMEM);

    mask_detect_kernel<<<1, 256>>>(maskraw);
    mask_convert_kernel<<<(Nc * Nc) / 256, 256>>>(maskraw);

    // split inputs into bf16 hi/lo
    const int xN4 = (Mtot * DIMc) / 4;       // 2097152
    const int wN4 = (DIMc * DIMc) / 4;       // 262144
    split_kernel<<<xN4 / 256, 256>>>(x,  (unsigned*)xh,  (unsigned*)xl,  xN4);
    split_kernel<<<wN4 / 256, 256>>>(Wq, (unsigned*)wqh, (unsigned*)wql, wN4);
    split_kernel<<<wN4 / 256, 256>>>(Wk, (unsigned*)wkh, (unsigned*)wkl, wN4);
    split_kernel<<<wN4 / 256, 256>>>(Wv, (unsigned*)wvh, (unsigned*)wvl, wN4);
    split_kernel<<<wN4 / 256, 256>>>(Wo, (unsigned*)woh, (unsigned*)wol, wN4);

    dim3 gqkv(DIMc / 128, Mtot / 128, 3);
    gemm_async<1><<<gqkv, 256, GEMM_SMEM>>>(xh, xl, wqh, wql, wkh, wkl, wvh, wvl,
                                            gq, gk, gv);

    qknorm_rope_kernel<<<(Bc * Hc * Nc) / 4, 128>>>(qg, kg, cost, sint, ridx);

    attn_kernel<<<dim3(Nc / 64, Hc, Bc), 128>>>();

    dim3 gout(DIMc / 128, Mtot / 128, 1);
    gemm_async<0><<<gout, 256, GEMM_SMEM>>>(aoh, aol, woh, wol,
                                            nullptr, nullptr, nullptr, nullptr,
                                            out, nullptr, nullptr);
}